// round 10
// baseline (speedup 1.0000x reference)
#include <cuda_runtime.h>
#include <math.h>

#define HH 512
#define WW 512
#define CHW 128
#define FHW 256
#define CF 256
#define NCc 3
#define NPTS 2048
#define NUM_OVER 6144
#define CHUNK 6
#define STEP1 1536
#define STEP2 512
#define BB 2
#define FEAT_DIM 259
#define FEAT_PAD 260
#define NCB1 65
#define NROWS (BB*NPTS)
#define FINE_FLAT (BB*NPTS*CF)
#define OUT_OFF (BB*NCc*NPTS)
#define MASK_SIZE (BB*HH*WW)
#define RPB 16
#define NPAIR (RPB/2)
#define NWORDS (HH*WW/32)
#define W1P_ELEMS (NCB1*256*4)
#define W2P_ELEMS (NCB1*128*4)
#define PREP_SEL_BLOCKS 2
#define PREP_REPACK_BLOCKS 98
#define P_MAX 18
#define STAGE_FL 4096                      // 4 pts x 4 taps x 256 ch per buffer
#define NBUF 4

// ---------------- device scratch ----------------
__device__ int   g_pts[BB*NPTS];
__device__ float g_cflat[BB*NPTS*NCc];
__device__ float g_w1p[W1P_ELEMS];
__device__ float g_w2p[W2P_ELEMS];

// ---------------- f32x2 helpers ----------------
__device__ __forceinline__ unsigned long long pk2(float lo, float hi) {
    unsigned long long r;
    asm("mov.b64 %0, {%1,%2};" : "=l"(r) : "f"(lo), "f"(hi));
    return r;
}
__device__ __forceinline__ void upk2(unsigned long long v, float& lo, float& hi) {
    asm("mov.b64 {%0,%1}, %2;" : "=f"(lo), "=f"(hi) : "l"(v));
}
__device__ __forceinline__ void fma2(unsigned long long& d, unsigned long long a,
                                     unsigned long long b) {
    asm("fma.rn.f32x2 %0, %1, %2, %0;" : "+l"(d) : "l"(a), "l"(b));
}
// ---------------- cp.async helpers ----------------
__device__ __forceinline__ void cpa4(unsigned int dst, const float* src) {
    asm volatile("cp.async.ca.shared.global [%0], [%1], 4;" :: "r"(dst), "l"(src));
}
#define CPA_COMMIT() asm volatile("cp.async.commit_group;" ::: "memory")

// =========================================================================
// k_prep (unchanged, passing): radix-threshold selection + ordered emit +
// mask + coarse logits; extra blocks repack weights.
// =========================================================================
__global__ __launch_bounds__(1024) void k_prep(const float* __restrict__ coarse,
                                               const int* __restrict__ rnd,
                                               const float* __restrict__ w1,
                                               const float* __restrict__ w2,
                                               float* __restrict__ mask_out) {
    extern __shared__ unsigned int dyn[];
    __shared__ int hist[256];
    __shared__ int sfxsum[257];
    __shared__ int warp_tot[32];
    __shared__ unsigned int s_prefix;
    __shared__ int s_need;

    if (blockIdx.x >= PREP_SEL_BLOCKS) {
        int t = (blockIdx.x - PREP_SEL_BLOCKS) * 1024 + threadIdx.x;
        if (t < W1P_ELEMS) {
            int cb = t >> 10, rest = t & 1023;
            int o = rest >> 2, q = rest & 3, c = cb * 4 + q;
            g_w1p[t] = (c < FEAT_DIM) ? w1[o*FEAT_DIM + c] : 0.f;
        } else {
            int t2 = t - W1P_ELEMS;
            if (t2 < W2P_ELEMS) {
                int cb = t2 >> 9, rest = t2 & 511;
                int o = rest >> 2, q = rest & 3, c = cb * 4 + q;
                g_w2p[t2] = (c < FEAT_DIM) ? w2[o*FEAT_DIM + c] : 0.f;
            }
        }
        return;
    }

    int b = blockIdx.x;
    int tid = threadIdx.x;
    int lane = tid & 31, wrp = tid >> 5;

    for (int jj = 0; jj < CHUNK; jj++) {
        int j = tid * CHUNK + jj;
        int idx = rnd[j];
        int h = idx / WW, w = idx % WW;
        float yc = (float)h * 0.25f - 0.375f;
        float xc = (float)w * 0.25f - 0.375f;
        int y0 = (int)floorf(yc); float fy = yc - (float)y0;
        int x0 = (int)floorf(xc); float fx = xc - (float)x0;
        int y0c = min(max(y0,   0), CHW-1), y1c = min(max(y0+1, 0), CHW-1);
        int x0c = min(max(x0,   0), CHW-1), x1c = min(max(x0+1, 0), CHW-1);
        float p[3];
        const float* base = coarse + (size_t)b * NCc * CHW * CHW;
#pragma unroll
        for (int c = 0; c < 3; c++) {
            const float* pc = base + c * CHW * CHW;
            float v00 = pc[y0c*CHW + x0c], v01 = pc[y0c*CHW + x1c];
            float v10 = pc[y1c*CHW + x0c], v11 = pc[y1c*CHW + x1c];
            float top = v00 * (1.f - fx) + v01 * fx;
            float bot = v10 * (1.f - fx) + v11 * fx;
            p[c] = top * (1.f - fy) + bot * fy;
        }
        float m  = fmaxf(p[0], fmaxf(p[1], p[2]));
        float e0 = expf(p[0]-m), e1 = expf(p[1]-m), e2 = expf(p[2]-m);
        float s  = e0 + e1 + e2;
        float q0 = e0/s, q1 = e1/s, q2 = e2/s;
        float mx  = fmaxf(q0, fmaxf(q1, q2));
        float mn  = fminf(q0, fminf(q1, q2));
        float mid = q0 + q1 + q2 - mx - mn;
        float u = 1.0f - (mx - mid);
        unsigned int bits = __float_as_uint(u);
        dyn[j] = bits ^ ((bits >> 31) ? 0xFFFFFFFFu : 0x80000000u);
    }
    if (tid == 0) { s_prefix = 0u; s_need = STEP1; }
    __syncthreads();

    for (int lvl = 0; lvl < 4; lvl++) {
        int shift = 24 - 8*lvl;
        unsigned int hi_mask = lvl ? (0xFFFFFFFFu << (shift + 8)) : 0u;
        unsigned int pref = s_prefix;
        int need = s_need;
        if (tid < 256) hist[tid] = 0;
        __syncthreads();
#pragma unroll
        for (int jj = 0; jj < CHUNK; jj++) {
            unsigned int ok = dyn[tid*CHUNK + jj];
            if ((ok & hi_mask) == pref) atomicAdd(&hist[(ok >> shift) & 255], 1);
        }
        __syncthreads();
        int x = (tid < 256) ? hist[255 - tid] : 0;
#pragma unroll
        for (int o = 1; o < 32; o <<= 1) {
            int y = __shfl_up_sync(0xFFFFFFFFu, x, o);
            if (lane >= o) x += y;
        }
        if (tid < 256 && lane == 31) warp_tot[wrp] = x;
        __syncthreads();
        if (tid < 256) {
            int basew = 0;
            for (int wq = 0; wq < wrp; wq++) basew += warp_tot[wq];
            sfxsum[255 - tid] = x + basew;
        }
        __syncthreads();
        if (tid < 256) {
            int S  = sfxsum[tid];
            int S1 = (tid == 255) ? 0 : sfxsum[tid + 1];
            if (S >= need && S1 < need) {
                s_prefix = pref | ((unsigned int)tid << shift);
                s_need = need - S1;
            }
        }
        __syncthreads();
    }
    unsigned int T = s_prefix;
    int need = s_need;

    unsigned int okv[CHUNK];
    int localeq = 0;
#pragma unroll
    for (int jj = 0; jj < CHUNK; jj++) {
        okv[jj] = dyn[tid*CHUNK + jj];
        localeq += (okv[jj] == T);
    }
    {
        int x = localeq;
#pragma unroll
        for (int o = 1; o < 32; o <<= 1) {
            int y = __shfl_up_sync(0xFFFFFFFFu, x, o);
            if (lane >= o) x += y;
        }
        if (lane == 31) warp_tot[wrp] = x;
        __syncthreads();
        int basew = 0;
        for (int wq = 0; wq < wrp; wq++) basew += warp_tot[wq];
        int rank = basew + x - localeq;
        unsigned int selmask = 0;
#pragma unroll
        for (int jj = 0; jj < CHUNK; jj++) {
            bool sel = okv[jj] > T;
            if (okv[jj] == T) { sel = (rank < need); rank++; }
            if (sel) selmask |= 1u << jj;
        }
        __syncthreads();
        for (int w = tid; w < NWORDS; w += 1024) dyn[w] = 0u;
        __syncthreads();
#pragma unroll
        for (int jj = 0; jj < CHUNK; jj++)
            if ((selmask >> jj) & 1u) {
                int lin = rnd[tid*CHUNK + jj];
                atomicOr(&dyn[lin >> 5], 1u << (lin & 31));
            }
    }
    for (int i = tid; i < STEP2; i += 1024) {
        int lin = rnd[HH*WW - STEP2 + i];
        atomicOr(&dyn[lin >> 5], 1u << (lin & 31));
    }
    __syncthreads();

    {
        int w0 = tid * 8;
        unsigned int words[8];
        int cnt = 0;
#pragma unroll
        for (int q = 0; q < 8; q++) { words[q] = dyn[w0 + q]; cnt += __popc(words[q]); }
        int incl = cnt;
#pragma unroll
        for (int o = 1; o < 32; o <<= 1) {
            int v = __shfl_up_sync(0xFFFFFFFFu, incl, o);
            if (lane >= o) incl += v;
        }
        if (lane == 31) warp_tot[wrp] = incl;
        __syncthreads();
        int basew = 0;
        for (int wq = 0; wq < wrp; wq++) basew += warp_tot[wq];
        int offset = basew + incl - cnt;
#pragma unroll
        for (int q = 0; q < 8; q++) {
            unsigned int m = words[q];
            int linbase = (w0 + q) * 32;
            while (m) {
                int bpos = __ffs(m) - 1; m &= m - 1;
                int lin = linbase + bpos;
                g_pts[b*NPTS + offset] = lin;
                mask_out[b*HH*WW + lin] = 1.0f;
                offset++;
            }
        }
    }
    __syncthreads();

    for (int t = tid; t < NPTS; t += 1024) {
        int lin = g_pts[b*NPTS + t];
        int h = lin >> 9, w = lin & 511;
        float yc = (float)h * 0.25f - 0.375f;
        float xc = (float)w * 0.25f - 0.375f;
        int cy = (int)floorf(yc); float cfy = yc - (float)cy;
        int cx = (int)floorf(xc); float cfx = xc - (float)cx;
        int cy0 = min(max(cy,   0), CHW-1), cy1 = min(max(cy+1, 0), CHW-1);
        int cx0 = min(max(cx,   0), CHW-1), cx1 = min(max(cx+1, 0), CHW-1);
#pragma unroll
        for (int c = 0; c < 3; c++) {
            const float* pc = coarse + ((size_t)b * NCc + c) * (CHW * CHW);
            float v00 = pc[cy0*CHW + cx0], v01 = pc[cy0*CHW + cx1];
            float v10 = pc[cy1*CHW + cx0], v11 = pc[cy1*CHW + cx1];
            float top = v00 * (1.f - cfx) + v01 * cfx;
            float bot = v10 * (1.f - cfx) + v11 * cfx;
            g_cflat[(b*NPTS + t)*NCc + c] = top * (1.f - cfy) + bot * cfy;
        }
    }
}

// =========================================================================
// k_smlp: fused gather + MLP, 256 threads, 16 rows/block.
// Gather: 4-deep cp.async (LDGSTS) pipeline — groups of 4 points x 4 taps x
// 1 float/thread staged to smem; no register scoreboard cap on in-flight
// loads. Each thread consumes only its own staged channel (no block sync
// in the pipeline). Math formula identical to R6 -> bit-identical output.
// =========================================================================
__global__ __launch_bounds__(256) void k_smlp(const float* __restrict__ fine,
                                              const float* __restrict__ w3,
                                              const float* __restrict__ pa,
                                              float* __restrict__ out) {
    extern __shared__ float sm[];
    float* xsp   = sm;                                  // 8 pairs x 260 x2
    float* l1p   = xsp + NPAIR*FEAT_PAD*2;              // 8 pairs x 260 x2
    float* l2s   = l1p + NPAIR*FEAT_PAD*2;              // 16 x 128
    float* w3s   = l2s + RPB*128;                       // 396 (+4 pad)
    float* stage = w3s + 400;                           // NBUF x 4096
    __shared__ int   c_b[P_MAX], c_y0[P_MAX], c_y1[P_MAX],
                     c_x0[P_MAX], c_x1[P_MAX];
    __shared__ float c_fy[P_MAX], c_fx[P_MAX];

    int tid = threadIdx.x;
    int g0 = blockIdx.x * RPB;
    float a = *pa;

    int f0 = g0 * FEAT_DIM;
    int f1 = (g0 + RPB) * FEAT_DIM - 1;
    int p_lo = 0, np = 0;
    if (f0 < FINE_FLAT) {
        p_lo = f0 >> 8;
        np = (min(f1, FINE_FLAT - 1) >> 8) - p_lo + 1;
    }

    // ---- setup: coords; coarse fill; w3 -> smem ----
    if (tid < np) {
        int p = p_lo + tid;
        int idx = g_pts[p];
        int h = idx >> 9, w = idx & 511;
        float yf = (float)h * 0.5f - 0.25f;
        float xf = (float)w * 0.5f - 0.25f;
        int y0 = (int)floorf(yf); c_fy[tid] = yf - (float)y0;
        int x0 = (int)floorf(xf); c_fx[tid] = xf - (float)x0;
        c_y0[tid] = min(max(y0,   0), FHW-1); c_y1[tid] = min(max(y0+1, 0), FHW-1);
        c_x0[tid] = min(max(x0,   0), FHW-1); c_x1[tid] = min(max(x0+1, 0), FHW-1);
        c_b[tid] = p >> 11;
    }
    for (int t = tid; t < RPB*FEAT_PAD; t += 256) {
        int r = t & 15, c = t >> 4;
        int pi = ((r >> 1) * FEAT_PAD + c) * 2 + (r & 1);
        if (c >= FEAT_DIM) {
            xsp[pi] = 0.f;
        } else {
            int f = (g0 + r) * FEAT_DIM + c;
            if (f >= FINE_FLAT) xsp[pi] = g_cflat[f - FINE_FLAT];
        }
    }
    for (int t = tid; t < NCc*131; t += 256) w3s[t] = w3[t];
    __syncthreads();

    // ---- gather via pipelined cp.async ----
    {
        unsigned int stbase =
            (unsigned int)__cvta_generic_to_shared(stage) + (unsigned int)tid * 4u;
        int ngr = (np + 3) >> 2;

        // issue_group(g): 4 points x 4 taps, 4B each, into buffer g & 3
        auto issue_group = [&](int g) {
            int buf = g & (NBUF - 1);
            unsigned int d0 = stbase + (unsigned int)(buf * STAGE_FL) * 4u;
#pragma unroll
            for (int j = 0; j < 4; j++) {
                int i = min(g*4 + j, np - 1);
                const float* pf = fine + ((size_t)c_b[i] * CF + tid) * (FHW*FHW);
                unsigned int d = d0 + (unsigned int)(j * 4 * 256) * 4u;
                cpa4(d +    0u, pf + c_y0[i]*FHW + c_x0[i]);
                cpa4(d + 1024u, pf + c_y0[i]*FHW + c_x1[i]);
                cpa4(d + 2048u, pf + c_y1[i]*FHW + c_x0[i]);
                cpa4(d + 3072u, pf + c_y1[i]*FHW + c_x1[i]);
            }
            CPA_COMMIT();
        };

        int gp = 0;
        for (; gp < NBUF - 1 && gp < ngr; gp++) issue_group(gp);
        for (int g = 0; g < ngr; g++) {
            if (gp < ngr) { issue_group(gp); gp++; }
            int pend = gp - g;               // groups in flight incl. g
            if (pend >= 4)      asm volatile("cp.async.wait_group 3;" ::: "memory");
            else if (pend == 3) asm volatile("cp.async.wait_group 2;" ::: "memory");
            else if (pend == 2) asm volatile("cp.async.wait_group 1;" ::: "memory");
            else                asm volatile("cp.async.wait_group 0;" ::: "memory");
            int buf = g & (NBUF - 1);
            const float* st = stage + buf * STAGE_FL + tid;
#pragma unroll
            for (int j = 0; j < 4; j++) {
                int i = g*4 + j;
                if (i >= np) break;
                float v00 = st[(j*4 + 0)*256];
                float v01 = st[(j*4 + 1)*256];
                float v10 = st[(j*4 + 2)*256];
                float v11 = st[(j*4 + 3)*256];
                float sfx = c_fx[i], sfy = c_fy[i];
                float top = v00 * (1.f - sfx) + v01 * sfx;
                float bot = v10 * (1.f - sfx) + v11 * sfx;
                float v = top * (1.f - sfy) + bot * sfy;
                int rel = (p_lo + i) * 256 + tid - f0;
                if (rel >= 0 && rel < RPB*FEAT_DIM) {
                    int r = rel / FEAT_DIM, c = rel % FEAT_DIM;
                    xsp[((r >> 1) * FEAT_PAD + c) * 2 + (r & 1)] = v;
                }
            }
        }
    }
    __syncthreads();   // gather complete before anyone reads xsp

    // ---- tail copy: l1p[c>=256] = xsp[c>=256] (feeds layer 2) ----
    if (tid < NPAIR*8) {
        int pr = tid >> 3, rem = tid & 7;
        int c = 256 + (rem >> 1), lane2 = rem & 1;
        int pi = (pr*FEAT_PAD + c)*2 + lane2;
        l1p[pi] = xsp[pi];
    }

    // ---- layer 1: 259 -> 256, prelu (FFMA2, 8 pairs/thread) ----
    {
        int o = tid;
        unsigned long long accp[NPAIR];
#pragma unroll
        for (int pr = 0; pr < NPAIR; pr++) accp[pr] = 0ull;
        const float4* w1p4 = (const float4*)g_w1p;
#pragma unroll 2
        for (int cb = 0; cb < NCB1; cb++) {
            float4 wv = w1p4[cb*256 + o];
            unsigned long long wp0 = pk2(wv.x, wv.x), wp1 = pk2(wv.y, wv.y);
            unsigned long long wp2 = pk2(wv.z, wv.z), wp3 = pk2(wv.w, wv.w);
#pragma unroll
            for (int pr = 0; pr < NPAIR; pr++) {
                const ulonglong2* xp =
                    (const ulonglong2*)&xsp[(pr*FEAT_PAD + cb*4) * 2];
                ulonglong2 u0 = xp[0], u1 = xp[1];
                fma2(accp[pr], wp0, u0.x);
                fma2(accp[pr], wp1, u0.y);
                fma2(accp[pr], wp2, u1.x);
                fma2(accp[pr], wp3, u1.y);
            }
        }
#pragma unroll
        for (int pr = 0; pr < NPAIR; pr++) {
            float lo, hi; upk2(accp[pr], lo, hi);
            lo = lo >= 0.f ? lo : a * lo;
            hi = hi >= 0.f ? hi : a * hi;
            ((float2*)l1p)[pr*FEAT_PAD + o] = make_float2(lo, hi);
        }
    }
    __syncthreads();

    // ---- layer 2: 259 -> 128, prelu (half owns 4 pairs) ----
    {
        int o2 = tid & 127;
        int rh = tid >> 7;
        unsigned long long acc2[4];
#pragma unroll
        for (int pp = 0; pp < 4; pp++) acc2[pp] = 0ull;
        const float4* w2p4 = (const float4*)g_w2p;
#pragma unroll 2
        for (int cb = 0; cb < NCB1; cb++) {
            float4 wv = w2p4[cb*128 + o2];
            unsigned long long wp0 = pk2(wv.x, wv.x), wp1 = pk2(wv.y, wv.y);
            unsigned long long wp2 = pk2(wv.z, wv.z), wp3 = pk2(wv.w, wv.w);
#pragma unroll
            for (int pp = 0; pp < 4; pp++) {
                int pr = rh*4 + pp;
                const ulonglong2* xp =
                    (const ulonglong2*)&l1p[(pr*FEAT_PAD + cb*4) * 2];
                ulonglong2 u0 = xp[0], u1 = xp[1];
                fma2(acc2[pp], wp0, u0.x);
                fma2(acc2[pp], wp1, u0.y);
                fma2(acc2[pp], wp2, u1.x);
                fma2(acc2[pp], wp3, u1.y);
            }
        }
#pragma unroll
        for (int pp = 0; pp < 4; pp++) {
            int pr = rh*4 + pp;
            float lo, hi; upk2(acc2[pp], lo, hi);
            lo = lo >= 0.f ? lo : a * lo;
            hi = hi >= 0.f ? hi : a * hi;
            l2s[(2*pr  )*128 + o2] = lo;
            l2s[(2*pr+1)*128 + o2] = hi;
        }
    }
    __syncthreads();

    // ---- layer 3: 131 -> 3 (weights from smem) ----
    if (tid < RPB*NCc) {
        int r = tid / 3, oo = tid % 3;
        float s = 0.f;
        for (int c = 0; c < 128; c++) s = fmaf(w3s[oo*131 + c], l2s[r*128 + c], s);
#pragma unroll
        for (int t = 0; t < 3; t++) {
            float xt = xsp[((r >> 1)*FEAT_PAD + 256 + t)*2 + (r & 1)];
            s = fmaf(w3s[oo*131 + 128 + t], xt, s);
        }
        int g = g0 + r;
        int b = g >> 11, n = g & 2047;
        out[(b*NCc + oo)*NPTS + n] = s;
    }
}

// ---------------- launch ----------------
extern "C" void kernel_launch(void* const* d_in, const int* in_sizes, int n_in,
                              void* d_out, int out_size) {
    const float* fine   = (const float*)d_in[0];
    const float* coarse = (const float*)d_in[1];
    const float* w1     = (const float*)d_in[2];
    const float* w2     = (const float*)d_in[3];
    const float* w3     = (const float*)d_in[4];
    const float* pa     = (const float*)d_in[5];
    const int*   rnd    = (const int*)d_in[6];
    float* out = (float*)d_out;

    static int configured = 0;
    int smlp_smem = (2*NPAIR*FEAT_PAD*2 + RPB*128 + 400 + NBUF*STAGE_FL)
                    * (int)sizeof(float);
    if (!configured) {
        cudaFuncSetAttribute(k_prep, cudaFuncAttributeMaxDynamicSharedMemorySize,
                             NWORDS * (int)sizeof(unsigned int));
        cudaFuncSetAttribute(k_smlp, cudaFuncAttributeMaxDynamicSharedMemorySize,
                             smlp_smem);
        configured = 1;
    }

    cudaMemsetAsync(out + OUT_OFF, 0, (size_t)MASK_SIZE * sizeof(float), 0);
    k_prep<<<PREP_SEL_BLOCKS + PREP_REPACK_BLOCKS, 1024,
             NWORDS * sizeof(unsigned int)>>>(coarse, rnd, w1, w2, out + OUT_OFF);
    k_smlp<<<NROWS/RPB, 256, smlp_smem>>>(fine, w3, pa, out);
    (void)in_sizes; (void)n_in; (void)out_size;
}

// round 11
// speedup vs baseline: 1.2841x; 1.2841x over previous
#include <cuda_runtime.h>
#include <math.h>

#define HH 512
#define WW 512
#define CHW 128
#define FHW 256
#define CF 256
#define NCc 3
#define NPTS 2048
#define NUM_OVER 6144
#define CHUNK 6
#define STEP1 1536
#define STEP2 512
#define BB 2
#define FEAT_DIM 259
#define FEAT_PAD 260
#define NCB1 65
#define NROWS (BB*NPTS)
#define FINE_FLAT (BB*NPTS*CF)
#define OUT_OFF (BB*NCc*NPTS)
#define MASK_SIZE (BB*HH*WW)
#define RPB 16
#define NPAIR (RPB/2)
#define NWORDS (HH*WW/32)
#define W1P_ELEMS (NCB1*256*4)
#define W2P_ELEMS (NCB1*128*4)
#define PREP_SEL_BLOCKS 2
#define PREP_REPACK_BLOCKS 98

// ---------------- device scratch ----------------
__device__ int   g_pts[BB*NPTS];
__device__ float g_cflat[BB*NPTS*NCc];
__device__ float g_flat[FINE_FLAT];          // [pt][ch], linear == flat index
__device__ float g_w1p[W1P_ELEMS];
__device__ float g_w2p[W2P_ELEMS];

// ---------------- f32x2 helpers ----------------
__device__ __forceinline__ unsigned long long pk2(float lo, float hi) {
    unsigned long long r;
    asm("mov.b64 %0, {%1,%2};" : "=l"(r) : "f"(lo), "f"(hi));
    return r;
}
__device__ __forceinline__ void upk2(unsigned long long v, float& lo, float& hi) {
    asm("mov.b64 {%0,%1}, %2;" : "=f"(lo), "=f"(hi) : "l"(v));
}
__device__ __forceinline__ void fma2(unsigned long long& d, unsigned long long a,
                                     unsigned long long b) {
    asm("fma.rn.f32x2 %0, %1, %2, %0;" : "+l"(d) : "l"(a), "l"(b));
}

// =========================================================================
// k_prep (unchanged, passing): radix-threshold selection + ordered emit +
// mask + coarse logits; extra blocks repack weights.
// =========================================================================
__global__ __launch_bounds__(1024) void k_prep(const float* __restrict__ coarse,
                                               const int* __restrict__ rnd,
                                               const float* __restrict__ w1,
                                               const float* __restrict__ w2,
                                               float* __restrict__ mask_out) {
    extern __shared__ unsigned int dyn[];
    __shared__ int hist[256];
    __shared__ int sfxsum[257];
    __shared__ int warp_tot[32];
    __shared__ unsigned int s_prefix;
    __shared__ int s_need;

    if (blockIdx.x >= PREP_SEL_BLOCKS) {
        int t = (blockIdx.x - PREP_SEL_BLOCKS) * 1024 + threadIdx.x;
        if (t < W1P_ELEMS) {
            int cb = t >> 10, rest = t & 1023;
            int o = rest >> 2, q = rest & 3, c = cb * 4 + q;
            g_w1p[t] = (c < FEAT_DIM) ? w1[o*FEAT_DIM + c] : 0.f;
        } else {
            int t2 = t - W1P_ELEMS;
            if (t2 < W2P_ELEMS) {
                int cb = t2 >> 9, rest = t2 & 511;
                int o = rest >> 2, q = rest & 3, c = cb * 4 + q;
                g_w2p[t2] = (c < FEAT_DIM) ? w2[o*FEAT_DIM + c] : 0.f;
            }
        }
        return;
    }

    int b = blockIdx.x;
    int tid = threadIdx.x;
    int lane = tid & 31, wrp = tid >> 5;

    for (int jj = 0; jj < CHUNK; jj++) {
        int j = tid * CHUNK + jj;
        int idx = rnd[j];
        int h = idx / WW, w = idx % WW;
        float yc = (float)h * 0.25f - 0.375f;
        float xc = (float)w * 0.25f - 0.375f;
        int y0 = (int)floorf(yc); float fy = yc - (float)y0;
        int x0 = (int)floorf(xc); float fx = xc - (float)x0;
        int y0c = min(max(y0,   0), CHW-1), y1c = min(max(y0+1, 0), CHW-1);
        int x0c = min(max(x0,   0), CHW-1), x1c = min(max(x0+1, 0), CHW-1);
        float p[3];
        const float* base = coarse + (size_t)b * NCc * CHW * CHW;
#pragma unroll
        for (int c = 0; c < 3; c++) {
            const float* pc = base + c * CHW * CHW;
            float v00 = pc[y0c*CHW + x0c], v01 = pc[y0c*CHW + x1c];
            float v10 = pc[y1c*CHW + x0c], v11 = pc[y1c*CHW + x1c];
            float top = v00 * (1.f - fx) + v01 * fx;
            float bot = v10 * (1.f - fx) + v11 * fx;
            p[c] = top * (1.f - fy) + bot * fy;
        }
        float m  = fmaxf(p[0], fmaxf(p[1], p[2]));
        float e0 = expf(p[0]-m), e1 = expf(p[1]-m), e2 = expf(p[2]-m);
        float s  = e0 + e1 + e2;
        float q0 = e0/s, q1 = e1/s, q2 = e2/s;
        float mx  = fmaxf(q0, fmaxf(q1, q2));
        float mn  = fminf(q0, fminf(q1, q2));
        float mid = q0 + q1 + q2 - mx - mn;
        float u = 1.0f - (mx - mid);
        unsigned int bits = __float_as_uint(u);
        dyn[j] = bits ^ ((bits >> 31) ? 0xFFFFFFFFu : 0x80000000u);
    }
    if (tid == 0) { s_prefix = 0u; s_need = STEP1; }
    __syncthreads();

    for (int lvl = 0; lvl < 4; lvl++) {
        int shift = 24 - 8*lvl;
        unsigned int hi_mask = lvl ? (0xFFFFFFFFu << (shift + 8)) : 0u;
        unsigned int pref = s_prefix;
        int need = s_need;
        if (tid < 256) hist[tid] = 0;
        __syncthreads();
#pragma unroll
        for (int jj = 0; jj < CHUNK; jj++) {
            unsigned int ok = dyn[tid*CHUNK + jj];
            if ((ok & hi_mask) == pref) atomicAdd(&hist[(ok >> shift) & 255], 1);
        }
        __syncthreads();
        int x = (tid < 256) ? hist[255 - tid] : 0;
#pragma unroll
        for (int o = 1; o < 32; o <<= 1) {
            int y = __shfl_up_sync(0xFFFFFFFFu, x, o);
            if (lane >= o) x += y;
        }
        if (tid < 256 && lane == 31) warp_tot[wrp] = x;
        __syncthreads();
        if (tid < 256) {
            int basew = 0;
            for (int wq = 0; wq < wrp; wq++) basew += warp_tot[wq];
            sfxsum[255 - tid] = x + basew;
        }
        __syncthreads();
        if (tid < 256) {
            int S  = sfxsum[tid];
            int S1 = (tid == 255) ? 0 : sfxsum[tid + 1];
            if (S >= need && S1 < need) {
                s_prefix = pref | ((unsigned int)tid << shift);
                s_need = need - S1;
            }
        }
        __syncthreads();
    }
    unsigned int T = s_prefix;
    int need = s_need;

    unsigned int okv[CHUNK];
    int localeq = 0;
#pragma unroll
    for (int jj = 0; jj < CHUNK; jj++) {
        okv[jj] = dyn[tid*CHUNK + jj];
        localeq += (okv[jj] == T);
    }
    {
        int x = localeq;
#pragma unroll
        for (int o = 1; o < 32; o <<= 1) {
            int y = __shfl_up_sync(0xFFFFFFFFu, x, o);
            if (lane >= o) x += y;
        }
        if (lane == 31) warp_tot[wrp] = x;
        __syncthreads();
        int basew = 0;
        for (int wq = 0; wq < wrp; wq++) basew += warp_tot[wq];
        int rank = basew + x - localeq;
        unsigned int selmask = 0;
#pragma unroll
        for (int jj = 0; jj < CHUNK; jj++) {
            bool sel = okv[jj] > T;
            if (okv[jj] == T) { sel = (rank < need); rank++; }
            if (sel) selmask |= 1u << jj;
        }
        __syncthreads();
        for (int w = tid; w < NWORDS; w += 1024) dyn[w] = 0u;
        __syncthreads();
#pragma unroll
        for (int jj = 0; jj < CHUNK; jj++)
            if ((selmask >> jj) & 1u) {
                int lin = rnd[tid*CHUNK + jj];
                atomicOr(&dyn[lin >> 5], 1u << (lin & 31));
            }
    }
    for (int i = tid; i < STEP2; i += 1024) {
        int lin = rnd[HH*WW - STEP2 + i];
        atomicOr(&dyn[lin >> 5], 1u << (lin & 31));
    }
    __syncthreads();

    {
        int w0 = tid * 8;
        unsigned int words[8];
        int cnt = 0;
#pragma unroll
        for (int q = 0; q < 8; q++) { words[q] = dyn[w0 + q]; cnt += __popc(words[q]); }
        int incl = cnt;
#pragma unroll
        for (int o = 1; o < 32; o <<= 1) {
            int v = __shfl_up_sync(0xFFFFFFFFu, incl, o);
            if (lane >= o) incl += v;
        }
        if (lane == 31) warp_tot[wrp] = incl;
        __syncthreads();
        int basew = 0;
        for (int wq = 0; wq < wrp; wq++) basew += warp_tot[wq];
        int offset = basew + incl - cnt;
#pragma unroll
        for (int q = 0; q < 8; q++) {
            unsigned int m = words[q];
            int linbase = (w0 + q) * 32;
            while (m) {
                int bpos = __ffs(m) - 1; m &= m - 1;
                int lin = linbase + bpos;
                g_pts[b*NPTS + offset] = lin;
                mask_out[b*HH*WW + lin] = 1.0f;
                offset++;
            }
        }
    }
    __syncthreads();

    for (int t = tid; t < NPTS; t += 1024) {
        int lin = g_pts[b*NPTS + t];
        int h = lin >> 9, w = lin & 511;
        float yc = (float)h * 0.25f - 0.375f;
        float xc = (float)w * 0.25f - 0.375f;
        int cy = (int)floorf(yc); float cfy = yc - (float)cy;
        int cx = (int)floorf(xc); float cfx = xc - (float)cx;
        int cy0 = min(max(cy,   0), CHW-1), cy1 = min(max(cy+1, 0), CHW-1);
        int cx0 = min(max(cx,   0), CHW-1), cx1 = min(max(cx+1, 0), CHW-1);
#pragma unroll
        for (int c = 0; c < 3; c++) {
            const float* pc = coarse + ((size_t)b * NCc + c) * (CHW * CHW);
            float v00 = pc[cy0*CHW + cx0], v01 = pc[cy0*CHW + cx1];
            float v10 = pc[cy1*CHW + cx0], v11 = pc[cy1*CHW + cx1];
            float top = v00 * (1.f - cfx) + v01 * cfx;
            float bot = v10 * (1.f - cfx) + v11 * cfx;
            g_cflat[(b*NPTS + t)*NCc + c] = top * (1.f - cfy) + bot * cfy;
        }
    }
}

// =========================================================================
// k_sample: one block per point, 256 threads = channels. No smem, no sync.
// Every thread computes the (block-uniform) coords itself, issues its 2-4
// loads immediately, writes one coalesced float to g_flat[pt*256+ch].
// ~32 warps/SM resident with block churn -> maximal loads in flight.
// =========================================================================
__global__ __launch_bounds__(256) void k_sample(const float* __restrict__ fine) {
    int g = blockIdx.x;                      // 0..4095 sorted point index
    int b = g >> 11;
    int ch = threadIdx.x;
    int idx = g_pts[g];                      // uniform
    int h = idx >> 9, w = idx & 511;
    float yf = (float)h * 0.5f - 0.25f;
    float xf = (float)w * 0.5f - 0.25f;
    int y0 = (int)floorf(yf); float sfy = yf - (float)y0;
    int x0 = (int)floorf(xf); float sfx = xf - (float)x0;
    int sy0 = min(max(y0,   0), FHW-1), sy1 = min(max(y0+1, 0), FHW-1);
    int sx0 = min(max(x0,   0), FHW-1), sx1 = min(max(x0+1, 0), FHW-1);
    const float* pf = fine + ((size_t)b * CF + ch) * (FHW * FHW);
    float v00, v01, v10, v11;
    if ((sx1 == sx0 + 1) && ((sx0 & 1) == 0)) {     // block-uniform branch
        float2 aa = *(const float2*)(pf + sy0*FHW + sx0);
        float2 dd = *(const float2*)(pf + sy1*FHW + sx0);
        v00 = aa.x; v01 = aa.y; v10 = dd.x; v11 = dd.y;
    } else {
        v00 = pf[sy0*FHW + sx0]; v01 = pf[sy0*FHW + sx1];
        v10 = pf[sy1*FHW + sx0]; v11 = pf[sy1*FHW + sx1];
    }
    float top = v00 * (1.f - sfx) + v01 * sfx;
    float bot = v10 * (1.f - sfx) + v11 * sfx;
    g_flat[(size_t)g * CF + ch] = top * (1.f - sfy) + bot * sfy;
}

// =========================================================================
// k_mlp: 16 rows/block, 256 threads, FFMA2 core (R6, bit-identical).
// Row load is LINEAR: flat index f=(g0+r)*259+c is the address in
// g_flat[pt][ch] order (fine region) / g_cflat (coarse region) — fully
// coalesced, L2-hot (just written by k_sample).
// =========================================================================
__global__ __launch_bounds__(256) void k_mlp(const float* __restrict__ w3,
                                             const float* __restrict__ pa,
                                             float* __restrict__ out) {
    extern __shared__ float sm[];
    float* xsp = sm;                                   // 8 pairs x 260 x2
    float* l1p = xsp + NPAIR*FEAT_PAD*2;               // 8 pairs x 260 x2
    float* l2s = l1p + NPAIR*FEAT_PAD*2;               // 16 x 128
    float* w3s = l2s + RPB*128;                        // 396 (+4 pad)

    int tid = threadIdx.x;
    int g0 = blockIdx.x * RPB;
    float a = *pa;

    // ---- load rows (coalesced) into the pair-interleaved tile ----
    for (int t = tid; t < RPB*FEAT_PAD; t += 256) {
        int r = t / FEAT_PAD, c = t - r*FEAT_PAD;
        float v = 0.f;
        if (c < FEAT_DIM) {
            int f = (g0 + r) * FEAT_DIM + c;
            v = (f < FINE_FLAT) ? g_flat[f] : g_cflat[f - FINE_FLAT];
        }
        int pi = ((r >> 1) * FEAT_PAD + c) * 2 + (r & 1);
        xsp[pi] = v;
        if (c >= 256) l1p[pi] = v;                     // tail feeds layer 2
    }
    for (int t = tid; t < NCc*131; t += 256) w3s[t] = w3[t];
    __syncthreads();

    // ---- layer 1: 259 -> 256, prelu (FFMA2, 8 pairs/thread) ----
    {
        int o = tid;
        unsigned long long accp[NPAIR];
#pragma unroll
        for (int pr = 0; pr < NPAIR; pr++) accp[pr] = 0ull;
        const float4* w1p4 = (const float4*)g_w1p;
#pragma unroll 2
        for (int cb = 0; cb < NCB1; cb++) {
            float4 wv = w1p4[cb*256 + o];
            unsigned long long wp0 = pk2(wv.x, wv.x), wp1 = pk2(wv.y, wv.y);
            unsigned long long wp2 = pk2(wv.z, wv.z), wp3 = pk2(wv.w, wv.w);
#pragma unroll
            for (int pr = 0; pr < NPAIR; pr++) {
                const ulonglong2* xp =
                    (const ulonglong2*)&xsp[(pr*FEAT_PAD + cb*4) * 2];
                ulonglong2 u0 = xp[0], u1 = xp[1];
                fma2(accp[pr], wp0, u0.x);
                fma2(accp[pr], wp1, u0.y);
                fma2(accp[pr], wp2, u1.x);
                fma2(accp[pr], wp3, u1.y);
            }
        }
#pragma unroll
        for (int pr = 0; pr < NPAIR; pr++) {
            float lo, hi; upk2(accp[pr], lo, hi);
            lo = lo >= 0.f ? lo : a * lo;
            hi = hi >= 0.f ? hi : a * hi;
            ((float2*)l1p)[pr*FEAT_PAD + o] = make_float2(lo, hi);
        }
    }
    __syncthreads();

    // ---- layer 2: 259 -> 128, prelu (half owns 4 pairs) ----
    {
        int o2 = tid & 127;
        int rh = tid >> 7;
        unsigned long long acc2[4];
#pragma unroll
        for (int pp = 0; pp < 4; pp++) acc2[pp] = 0ull;
        const float4* w2p4 = (const float4*)g_w2p;
#pragma unroll 2
        for (int cb = 0; cb < NCB1; cb++) {
            float4 wv = w2p4[cb*128 + o2];
            unsigned long long wp0 = pk2(wv.x, wv.x), wp1 = pk2(wv.y, wv.y);
            unsigned long long wp2 = pk2(wv.z, wv.z), wp3 = pk2(wv.w, wv.w);
#pragma unroll
            for (int pp = 0; pp < 4; pp++) {
                int pr = rh*4 + pp;
                const ulonglong2* xp =
                    (const ulonglong2*)&l1p[(pr*FEAT_PAD + cb*4) * 2];
                ulonglong2 u0 = xp[0], u1 = xp[1];
                fma2(acc2[pp], wp0, u0.x);
                fma2(acc2[pp], wp1, u0.y);
                fma2(acc2[pp], wp2, u1.x);
                fma2(acc2[pp], wp3, u1.y);
            }
        }
#pragma unroll
        for (int pp = 0; pp < 4; pp++) {
            int pr = rh*4 + pp;
            float lo, hi; upk2(acc2[pp], lo, hi);
            lo = lo >= 0.f ? lo : a * lo;
            hi = hi >= 0.f ? hi : a * hi;
            l2s[(2*pr  )*128 + o2] = lo;
            l2s[(2*pr+1)*128 + o2] = hi;
        }
    }
    __syncthreads();

    // ---- layer 3: 131 -> 3 (weights from smem) ----
    if (tid < RPB*NCc) {
        int r = tid / 3, oo = tid % 3;
        float s = 0.f;
        for (int c = 0; c < 128; c++) s = fmaf(w3s[oo*131 + c], l2s[r*128 + c], s);
#pragma unroll
        for (int t = 0; t < 3; t++) {
            float xt = xsp[((r >> 1)*FEAT_PAD + 256 + t)*2 + (r & 1)];
            s = fmaf(w3s[oo*131 + 128 + t], xt, s);
        }
        int g = g0 + r;
        int b = g >> 11, n = g & 2047;
        out[(b*NCc + oo)*NPTS + n] = s;
    }
}

// ---------------- launch ----------------
extern "C" void kernel_launch(void* const* d_in, const int* in_sizes, int n_in,
                              void* d_out, int out_size) {
    const float* fine   = (const float*)d_in[0];
    const float* coarse = (const float*)d_in[1];
    const float* w1     = (const float*)d_in[2];
    const float* w2     = (const float*)d_in[3];
    const float* w3     = (const float*)d_in[4];
    const float* pa     = (const float*)d_in[5];
    const int*   rnd    = (const int*)d_in[6];
    float* out = (float*)d_out;

    static int configured = 0;
    int mlp_smem = (2*NPAIR*FEAT_PAD*2 + RPB*128 + 400) * (int)sizeof(float);
    if (!configured) {
        cudaFuncSetAttribute(k_prep, cudaFuncAttributeMaxDynamicSharedMemorySize,
                             NWORDS * (int)sizeof(unsigned int));
        cudaFuncSetAttribute(k_mlp, cudaFuncAttributeMaxDynamicSharedMemorySize,
                             mlp_smem);
        configured = 1;
    }

    cudaMemsetAsync(out + OUT_OFF, 0, (size_t)MASK_SIZE * sizeof(float), 0);
    k_prep<<<PREP_SEL_BLOCKS + PREP_REPACK_BLOCKS, 1024,
             NWORDS * sizeof(unsigned int)>>>(coarse, rnd, w1, w2, out + OUT_OFF);
    k_sample<<<NROWS, 256>>>(fine);
    k_mlp<<<NROWS/RPB, 256, mlp_smem>>>(w3, pa, out);
    (void)in_sizes; (void)n_in; (void)out_size;
}

// round 12
// speedup vs baseline: 1.3884x; 1.0812x over previous
#include <cuda_runtime.h>
#include <math.h>

#define HH 512
#define WW 512
#define CHW 128
#define FHW 256
#define CF 256
#define NCc 3
#define NPTS 2048
#define NUM_OVER 6144
#define CHUNK 6
#define STEP1 1536
#define STEP2 512
#define BB 2
#define FEAT_DIM 259
#define FEAT_PAD 260
#define NCB1 65
#define NROWS (BB*NPTS)
#define FINE_FLAT (BB*NPTS*CF)
#define OUT_OFF (BB*NCc*NPTS)
#define MASK_SIZE (BB*HH*WW)
#define RPB 16
#define NPAIR (RPB/2)
#define NWORDS (HH*WW/32)
#define W1P_ELEMS (NCB1*256*4)
#define W2P_ELEMS (NCB1*128*4)
#define UNC_BLOCKS 12                        // 12288 keys / 1024
#define REPACK_BLOCKS 98

// ---------------- device scratch ----------------
__device__ int          g_pts[BB*NPTS];
__device__ unsigned int g_okey[BB*NUM_OVER];
__device__ float        g_cflat[BB*NPTS*NCc];
__device__ float        g_flat[FINE_FLAT];   // [pt][ch], linear == flat index
__device__ float        g_w1p[W1P_ELEMS];
__device__ float        g_w2p[W2P_ELEMS];

// ---------------- f32x2 helpers ----------------
__device__ __forceinline__ unsigned long long pk2(float lo, float hi) {
    unsigned long long r;
    asm("mov.b64 %0, {%1,%2};" : "=l"(r) : "f"(lo), "f"(hi));
    return r;
}
__device__ __forceinline__ void upk2(unsigned long long v, float& lo, float& hi) {
    asm("mov.b64 {%0,%1}, %2;" : "=f"(lo), "=f"(hi) : "l"(v));
}
__device__ __forceinline__ void fma2(unsigned long long& d, unsigned long long a,
                                     unsigned long long b) {
    asm("fma.rn.f32x2 %0, %1, %2, %0;" : "+l"(d) : "l"(a), "l"(b));
}

// =========================================================================
// k_unc: blocks 0..11  -> uncertainty keys (1 candidate/thread, parallel)
//        blocks 12..   -> weight repack
// Key arithmetic bit-identical to the passing kernels.
// =========================================================================
__global__ __launch_bounds__(1024) void k_unc(const float* __restrict__ coarse,
                                              const int* __restrict__ rnd,
                                              const float* __restrict__ w1,
                                              const float* __restrict__ w2) {
    if (blockIdx.x >= UNC_BLOCKS) {
        int t = (blockIdx.x - UNC_BLOCKS) * 1024 + threadIdx.x;
        if (t < W1P_ELEMS) {
            int cb = t >> 10, rest = t & 1023;
            int o = rest >> 2, q = rest & 3, c = cb * 4 + q;
            g_w1p[t] = (c < FEAT_DIM) ? w1[o*FEAT_DIM + c] : 0.f;
        } else {
            int t2 = t - W1P_ELEMS;
            if (t2 < W2P_ELEMS) {
                int cb = t2 >> 9, rest = t2 & 511;
                int o = rest >> 2, q = rest & 3, c = cb * 4 + q;
                g_w2p[t2] = (c < FEAT_DIM) ? w2[o*FEAT_DIM + c] : 0.f;
            }
        }
        return;
    }
    int t = blockIdx.x * 1024 + threadIdx.x;     // 0..12287
    int b = t / NUM_OVER, j = t - b * NUM_OVER;
    int idx = rnd[j];
    int h = idx / WW, w = idx % WW;
    float yc = (float)h * 0.25f - 0.375f;
    float xc = (float)w * 0.25f - 0.375f;
    int y0 = (int)floorf(yc); float fy = yc - (float)y0;
    int x0 = (int)floorf(xc); float fx = xc - (float)x0;
    int y0c = min(max(y0,   0), CHW-1), y1c = min(max(y0+1, 0), CHW-1);
    int x0c = min(max(x0,   0), CHW-1), x1c = min(max(x0+1, 0), CHW-1);
    float p[3];
    const float* base = coarse + (size_t)b * NCc * CHW * CHW;
#pragma unroll
    for (int c = 0; c < 3; c++) {
        const float* pc = base + c * CHW * CHW;
        float v00 = pc[y0c*CHW + x0c], v01 = pc[y0c*CHW + x1c];
        float v10 = pc[y1c*CHW + x0c], v11 = pc[y1c*CHW + x1c];
        float top = v00 * (1.f - fx) + v01 * fx;
        float bot = v10 * (1.f - fx) + v11 * fx;
        p[c] = top * (1.f - fy) + bot * fy;
    }
    float m  = fmaxf(p[0], fmaxf(p[1], p[2]));
    float e0 = expf(p[0]-m), e1 = expf(p[1]-m), e2 = expf(p[2]-m);
    float s  = e0 + e1 + e2;
    float q0 = e0/s, q1 = e1/s, q2 = e2/s;
    float mx  = fmaxf(q0, fmaxf(q1, q2));
    float mn  = fminf(q0, fminf(q1, q2));
    float mid = q0 + q1 + q2 - mx - mn;
    float u = 1.0f - (mx - mid);
    unsigned int bits = __float_as_uint(u);
    g_okey[t] = bits ^ ((bits >> 31) ? 0xFFFFFFFFu : 0x80000000u);
}

// =========================================================================
// k_sel: 2 blocks (one per batch). Loads keys coalesced into smem, then
// IDENTICAL radix-threshold + tie-rank + bitmap + ordered-emit logic.
// =========================================================================
__global__ __launch_bounds__(1024) void k_sel(const int* __restrict__ rnd,
                                              float* __restrict__ mask_out) {
    extern __shared__ unsigned int dyn[];        // 32KB: okey[6144] -> bitmap
    __shared__ int hist[256];
    __shared__ int sfxsum[257];
    __shared__ int warp_tot[32];
    __shared__ unsigned int s_prefix;
    __shared__ int s_need;

    int b = blockIdx.x;
    int tid = threadIdx.x;
    int lane = tid & 31, wrp = tid >> 5;

    for (int j = tid; j < NUM_OVER; j += 1024)
        dyn[j] = g_okey[b*NUM_OVER + j];
    if (tid == 0) { s_prefix = 0u; s_need = STEP1; }
    __syncthreads();

    for (int lvl = 0; lvl < 4; lvl++) {
        int shift = 24 - 8*lvl;
        unsigned int hi_mask = lvl ? (0xFFFFFFFFu << (shift + 8)) : 0u;
        unsigned int pref = s_prefix;
        int need = s_need;
        if (tid < 256) hist[tid] = 0;
        __syncthreads();
#pragma unroll
        for (int jj = 0; jj < CHUNK; jj++) {
            unsigned int ok = dyn[tid*CHUNK + jj];
            if ((ok & hi_mask) == pref) atomicAdd(&hist[(ok >> shift) & 255], 1);
        }
        __syncthreads();
        int x = (tid < 256) ? hist[255 - tid] : 0;
#pragma unroll
        for (int o = 1; o < 32; o <<= 1) {
            int y = __shfl_up_sync(0xFFFFFFFFu, x, o);
            if (lane >= o) x += y;
        }
        if (tid < 256 && lane == 31) warp_tot[wrp] = x;
        __syncthreads();
        if (tid < 256) {
            int basew = 0;
            for (int wq = 0; wq < wrp; wq++) basew += warp_tot[wq];
            sfxsum[255 - tid] = x + basew;
        }
        __syncthreads();
        if (tid < 256) {
            int S  = sfxsum[tid];
            int S1 = (tid == 255) ? 0 : sfxsum[tid + 1];
            if (S >= need && S1 < need) {
                s_prefix = pref | ((unsigned int)tid << shift);
                s_need = need - S1;
            }
        }
        __syncthreads();
    }
    unsigned int T = s_prefix;
    int need = s_need;

    unsigned int okv[CHUNK];
    int localeq = 0;
#pragma unroll
    for (int jj = 0; jj < CHUNK; jj++) {
        okv[jj] = dyn[tid*CHUNK + jj];
        localeq += (okv[jj] == T);
    }
    {
        int x = localeq;
#pragma unroll
        for (int o = 1; o < 32; o <<= 1) {
            int y = __shfl_up_sync(0xFFFFFFFFu, x, o);
            if (lane >= o) x += y;
        }
        if (lane == 31) warp_tot[wrp] = x;
        __syncthreads();
        int basew = 0;
        for (int wq = 0; wq < wrp; wq++) basew += warp_tot[wq];
        int rank = basew + x - localeq;
        unsigned int selmask = 0;
#pragma unroll
        for (int jj = 0; jj < CHUNK; jj++) {
            bool sel = okv[jj] > T;
            if (okv[jj] == T) { sel = (rank < need); rank++; }
            if (sel) selmask |= 1u << jj;
        }
        __syncthreads();
        for (int w = tid; w < NWORDS; w += 1024) dyn[w] = 0u;
        __syncthreads();
#pragma unroll
        for (int jj = 0; jj < CHUNK; jj++)
            if ((selmask >> jj) & 1u) {
                int lin = rnd[tid*CHUNK + jj];
                atomicOr(&dyn[lin >> 5], 1u << (lin & 31));
            }
    }
    for (int i = tid; i < STEP2; i += 1024) {
        int lin = rnd[HH*WW - STEP2 + i];
        atomicOr(&dyn[lin >> 5], 1u << (lin & 31));
    }
    __syncthreads();

    {
        int w0 = tid * 8;
        unsigned int words[8];
        int cnt = 0;
#pragma unroll
        for (int q = 0; q < 8; q++) { words[q] = dyn[w0 + q]; cnt += __popc(words[q]); }
        int incl = cnt;
#pragma unroll
        for (int o = 1; o < 32; o <<= 1) {
            int v = __shfl_up_sync(0xFFFFFFFFu, incl, o);
            if (lane >= o) incl += v;
        }
        if (lane == 31) warp_tot[wrp] = incl;
        __syncthreads();
        int basew = 0;
        for (int wq = 0; wq < wrp; wq++) basew += warp_tot[wq];
        int offset = basew + incl - cnt;
#pragma unroll
        for (int q = 0; q < 8; q++) {
            unsigned int m = words[q];
            int linbase = (w0 + q) * 32;
            while (m) {
                int bpos = __ffs(m) - 1; m &= m - 1;
                int lin = linbase + bpos;
                g_pts[b*NPTS + offset] = lin;
                mask_out[b*HH*WW + lin] = 1.0f;
                offset++;
            }
        }
    }
}

// =========================================================================
// k_sample: one block per point, 256 threads = channels. Threads 0..2 also
// compute the coarse logits for the point (coarse is L2-hot after k_unc).
// =========================================================================
__global__ __launch_bounds__(256) void k_sample(const float* __restrict__ fine,
                                                const float* __restrict__ coarse) {
    int g = blockIdx.x;                      // 0..4095 sorted point index
    int b = g >> 11;
    int ch = threadIdx.x;
    int idx = g_pts[g];                      // uniform
    int h = idx >> 9, w = idx & 511;
    float yf = (float)h * 0.5f - 0.25f;
    float xf = (float)w * 0.5f - 0.25f;
    int y0 = (int)floorf(yf); float sfy = yf - (float)y0;
    int x0 = (int)floorf(xf); float sfx = xf - (float)x0;
    int sy0 = min(max(y0,   0), FHW-1), sy1 = min(max(y0+1, 0), FHW-1);
    int sx0 = min(max(x0,   0), FHW-1), sx1 = min(max(x0+1, 0), FHW-1);
    const float* pf = fine + ((size_t)b * CF + ch) * (FHW * FHW);
    float v00, v01, v10, v11;
    if ((sx1 == sx0 + 1) && ((sx0 & 1) == 0)) {     // block-uniform branch
        float2 aa = *(const float2*)(pf + sy0*FHW + sx0);
        float2 dd = *(const float2*)(pf + sy1*FHW + sx0);
        v00 = aa.x; v01 = aa.y; v10 = dd.x; v11 = dd.y;
    } else {
        v00 = pf[sy0*FHW + sx0]; v01 = pf[sy0*FHW + sx1];
        v10 = pf[sy1*FHW + sx0]; v11 = pf[sy1*FHW + sx1];
    }
    float top = v00 * (1.f - sfx) + v01 * sfx;
    float bot = v10 * (1.f - sfx) + v11 * sfx;
    g_flat[(size_t)g * CF + ch] = top * (1.f - sfy) + bot * sfy;

    if (ch < NCc) {                           // coarse logits (3 threads)
        float yc = (float)h * 0.25f - 0.375f;
        float xc = (float)w * 0.25f - 0.375f;
        int cy = (int)floorf(yc); float cfy = yc - (float)cy;
        int cx = (int)floorf(xc); float cfx = xc - (float)cx;
        int cy0 = min(max(cy,   0), CHW-1), cy1 = min(max(cy+1, 0), CHW-1);
        int cx0 = min(max(cx,   0), CHW-1), cx1 = min(max(cx+1, 0), CHW-1);
        const float* pc = coarse + ((size_t)b * NCc + ch) * (CHW * CHW);
        float c00 = pc[cy0*CHW + cx0], c01 = pc[cy0*CHW + cx1];
        float c10 = pc[cy1*CHW + cx0], c11 = pc[cy1*CHW + cx1];
        float ctop = c00 * (1.f - cfx) + c01 * cfx;
        float cbot = c10 * (1.f - cfx) + c11 * cfx;
        g_cflat[g*NCc + ch] = ctop * (1.f - cfy) + cbot * cfy;
    }
}

// =========================================================================
// k_mlp (unchanged, passing): 16 rows/block, 256 threads, FFMA2 core.
// =========================================================================
__global__ __launch_bounds__(256) void k_mlp(const float* __restrict__ w3,
                                             const float* __restrict__ pa,
                                             float* __restrict__ out) {
    extern __shared__ float sm[];
    float* xsp = sm;
    float* l1p = xsp + NPAIR*FEAT_PAD*2;
    float* l2s = l1p + NPAIR*FEAT_PAD*2;
    float* w3s = l2s + RPB*128;

    int tid = threadIdx.x;
    int g0 = blockIdx.x * RPB;
    float a = *pa;

    for (int t = tid; t < RPB*FEAT_PAD; t += 256) {
        int r = t / FEAT_PAD, c = t - r*FEAT_PAD;
        float v = 0.f;
        if (c < FEAT_DIM) {
            int f = (g0 + r) * FEAT_DIM + c;
            v = (f < FINE_FLAT) ? g_flat[f] : g_cflat[f - FINE_FLAT];
        }
        int pi = ((r >> 1) * FEAT_PAD + c) * 2 + (r & 1);
        xsp[pi] = v;
        if (c >= 256) l1p[pi] = v;
    }
    for (int t = tid; t < NCc*131; t += 256) w3s[t] = w3[t];
    __syncthreads();

    {
        int o = tid;
        unsigned long long accp[NPAIR];
#pragma unroll
        for (int pr = 0; pr < NPAIR; pr++) accp[pr] = 0ull;
        const float4* w1p4 = (const float4*)g_w1p;
#pragma unroll 2
        for (int cb = 0; cb < NCB1; cb++) {
            float4 wv = w1p4[cb*256 + o];
            unsigned long long wp0 = pk2(wv.x, wv.x), wp1 = pk2(wv.y, wv.y);
            unsigned long long wp2 = pk2(wv.z, wv.z), wp3 = pk2(wv.w, wv.w);
#pragma unroll
            for (int pr = 0; pr < NPAIR; pr++) {
                const ulonglong2* xp =
                    (const ulonglong2*)&xsp[(pr*FEAT_PAD + cb*4) * 2];
                ulonglong2 u0 = xp[0], u1 = xp[1];
                fma2(accp[pr], wp0, u0.x);
                fma2(accp[pr], wp1, u0.y);
                fma2(accp[pr], wp2, u1.x);
                fma2(accp[pr], wp3, u1.y);
            }
        }
#pragma unroll
        for (int pr = 0; pr < NPAIR; pr++) {
            float lo, hi; upk2(accp[pr], lo, hi);
            lo = lo >= 0.f ? lo : a * lo;
            hi = hi >= 0.f ? hi : a * hi;
            ((float2*)l1p)[pr*FEAT_PAD + o] = make_float2(lo, hi);
        }
    }
    __syncthreads();

    {
        int o2 = tid & 127;
        int rh = tid >> 7;
        unsigned long long acc2[4];
#pragma unroll
        for (int pp = 0; pp < 4; pp++) acc2[pp] = 0ull;
        const float4* w2p4 = (const float4*)g_w2p;
#pragma unroll 2
        for (int cb = 0; cb < NCB1; cb++) {
            float4 wv = w2p4[cb*128 + o2];
            unsigned long long wp0 = pk2(wv.x, wv.x), wp1 = pk2(wv.y, wv.y);
            unsigned long long wp2 = pk2(wv.z, wv.z), wp3 = pk2(wv.w, wv.w);
#pragma unroll
            for (int pp = 0; pp < 4; pp++) {
                int pr = rh*4 + pp;
                const ulonglong2* xp =
                    (const ulonglong2*)&l1p[(pr*FEAT_PAD + cb*4) * 2];
                ulonglong2 u0 = xp[0], u1 = xp[1];
                fma2(acc2[pp], wp0, u0.x);
                fma2(acc2[pp], wp1, u0.y);
                fma2(acc2[pp], wp2, u1.x);
                fma2(acc2[pp], wp3, u1.y);
            }
        }
#pragma unroll
        for (int pp = 0; pp < 4; pp++) {
            int pr = rh*4 + pp;
            float lo, hi; upk2(acc2[pp], lo, hi);
            lo = lo >= 0.f ? lo : a * lo;
            hi = hi >= 0.f ? hi : a * hi;
            l2s[(2*pr  )*128 + o2] = lo;
            l2s[(2*pr+1)*128 + o2] = hi;
        }
    }
    __syncthreads();

    if (tid < RPB*NCc) {
        int r = tid / 3, oo = tid % 3;
        float s = 0.f;
        for (int c = 0; c < 128; c++) s = fmaf(w3s[oo*131 + c], l2s[r*128 + c], s);
#pragma unroll
        for (int t = 0; t < 3; t++) {
            float xt = xsp[((r >> 1)*FEAT_PAD + 256 + t)*2 + (r & 1)];
            s = fmaf(w3s[oo*131 + 128 + t], xt, s);
        }
        int g = g0 + r;
        int b = g >> 11, n = g & 2047;
        out[(b*NCc + oo)*NPTS + n] = s;
    }
}

// ---------------- launch ----------------
extern "C" void kernel_launch(void* const* d_in, const int* in_sizes, int n_in,
                              void* d_out, int out_size) {
    const float* fine   = (const float*)d_in[0];
    const float* coarse = (const float*)d_in[1];
    const float* w1     = (const float*)d_in[2];
    const float* w2     = (const float*)d_in[3];
    const float* w3     = (const float*)d_in[4];
    const float* pa     = (const float*)d_in[5];
    const int*   rnd    = (const int*)d_in[6];
    float* out = (float*)d_out;

    static int configured = 0;
    int mlp_smem = (2*NPAIR*FEAT_PAD*2 + RPB*128 + 400) * (int)sizeof(float);
    if (!configured) {
        cudaFuncSetAttribute(k_sel, cudaFuncAttributeMaxDynamicSharedMemorySize,
                             NWORDS * (int)sizeof(unsigned int));
        cudaFuncSetAttribute(k_mlp, cudaFuncAttributeMaxDynamicSharedMemorySize,
                             mlp_smem);
        configured = 1;
    }

    cudaMemsetAsync(out + OUT_OFF, 0, (size_t)MASK_SIZE * sizeof(float), 0);
    k_unc<<<UNC_BLOCKS + REPACK_BLOCKS, 1024>>>(coarse, rnd, w1, w2);
    k_sel<<<BB, 1024, NWORDS * sizeof(unsigned int)>>>(rnd, out + OUT_OFF);
    k_sample<<<NROWS, 256>>>(fine, coarse);
    k_mlp<<<NROWS/RPB, 256, mlp_smem>>>(w3, pa, out);
    (void)in_sizes; (void)n_in; (void)out_size;
}

// round 13
// speedup vs baseline: 1.4800x; 1.0660x over previous
#include <cuda_runtime.h>
#include <math.h>

#define HH 512
#define WW 512
#define CHW 128
#define FHW 256
#define CF 256
#define NCc 3
#define NPTS 2048
#define NUM_OVER 6144
#define CHUNK 6
#define STEP1 1536
#define STEP2 512
#define BB 2
#define FEAT_DIM 259
#define FEAT_PAD 260
#define NCB1 65
#define NROWS (BB*NPTS)
#define FINE_FLAT (BB*NPTS*CF)
#define OUT_OFF (BB*NCc*NPTS)
#define MASK_SIZE (BB*HH*WW)
#define RPB 16
#define HPAIR 4                              // pairs per half (8 rows)
#define HTILE (HPAIR*FEAT_PAD*2)             // floats per half tile
#define NWORDS (HH*WW/32)
#define W1P_ELEMS (NCB1*256*4)
#define W2P_ELEMS (NCB1*128*4)
#define UNC_BLOCKS 12
#define REPACK_BLOCKS 98

// ---------------- device scratch ----------------
__device__ int          g_pts[BB*NPTS];
__device__ unsigned int g_okey[BB*NUM_OVER];
__device__ float        g_cflat[BB*NPTS*NCc];
__device__ float        g_flat[FINE_FLAT];
__device__ float        g_w1p[W1P_ELEMS];
__device__ float        g_w2p[W2P_ELEMS];

// ---------------- f32x2 helpers ----------------
__device__ __forceinline__ unsigned long long pk2(float lo, float hi) {
    unsigned long long r;
    asm("mov.b64 %0, {%1,%2};" : "=l"(r) : "f"(lo), "f"(hi));
    return r;
}
__device__ __forceinline__ void upk2(unsigned long long v, float& lo, float& hi) {
    asm("mov.b64 {%0,%1}, %2;" : "=f"(lo), "=f"(hi) : "l"(v));
}
__device__ __forceinline__ void fma2(unsigned long long& d, unsigned long long a,
                                     unsigned long long b) {
    asm("fma.rn.f32x2 %0, %1, %2, %0;" : "+l"(d) : "l"(a), "l"(b));
}

// =========================================================================
// k_unc (unchanged): blocks 0..11 uncertainty keys; blocks 12.. repack.
// =========================================================================
__global__ __launch_bounds__(1024) void k_unc(const float* __restrict__ coarse,
                                              const int* __restrict__ rnd,
                                              const float* __restrict__ w1,
                                              const float* __restrict__ w2) {
    if (blockIdx.x >= UNC_BLOCKS) {
        int t = (blockIdx.x - UNC_BLOCKS) * 1024 + threadIdx.x;
        if (t < W1P_ELEMS) {
            int cb = t >> 10, rest = t & 1023;
            int o = rest >> 2, q = rest & 3, c = cb * 4 + q;
            g_w1p[t] = (c < FEAT_DIM) ? w1[o*FEAT_DIM + c] : 0.f;
        } else {
            int t2 = t - W1P_ELEMS;
            if (t2 < W2P_ELEMS) {
                int cb = t2 >> 9, rest = t2 & 511;
                int o = rest >> 2, q = rest & 3, c = cb * 4 + q;
                g_w2p[t2] = (c < FEAT_DIM) ? w2[o*FEAT_DIM + c] : 0.f;
            }
        }
        return;
    }
    int t = blockIdx.x * 1024 + threadIdx.x;
    int b = t / NUM_OVER, j = t - b * NUM_OVER;
    int idx = rnd[j];
    int h = idx / WW, w = idx % WW;
    float yc = (float)h * 0.25f - 0.375f;
    float xc = (float)w * 0.25f - 0.375f;
    int y0 = (int)floorf(yc); float fy = yc - (float)y0;
    int x0 = (int)floorf(xc); float fx = xc - (float)x0;
    int y0c = min(max(y0,   0), CHW-1), y1c = min(max(y0+1, 0), CHW-1);
    int x0c = min(max(x0,   0), CHW-1), x1c = min(max(x0+1, 0), CHW-1);
    float p[3];
    const float* base = coarse + (size_t)b * NCc * CHW * CHW;
#pragma unroll
    for (int c = 0; c < 3; c++) {
        const float* pc = base + c * CHW * CHW;
        float v00 = pc[y0c*CHW + x0c], v01 = pc[y0c*CHW + x1c];
        float v10 = pc[y1c*CHW + x0c], v11 = pc[y1c*CHW + x1c];
        float top = v00 * (1.f - fx) + v01 * fx;
        float bot = v10 * (1.f - fx) + v11 * fx;
        p[c] = top * (1.f - fy) + bot * fy;
    }
    float m  = fmaxf(p[0], fmaxf(p[1], p[2]));
    float e0 = expf(p[0]-m), e1 = expf(p[1]-m), e2 = expf(p[2]-m);
    float s  = e0 + e1 + e2;
    float q0 = e0/s, q1 = e1/s, q2 = e2/s;
    float mx  = fmaxf(q0, fmaxf(q1, q2));
    float mn  = fminf(q0, fminf(q1, q2));
    float mid = q0 + q1 + q2 - mx - mn;
    float u = 1.0f - (mx - mid);
    unsigned int bits = __float_as_uint(u);
    g_okey[t] = bits ^ ((bits >> 31) ? 0xFFFFFFFFu : 0x80000000u);
}

// =========================================================================
// k_sel (unchanged): 2 blocks, radix threshold + bitmap + ordered emit.
// =========================================================================
__global__ __launch_bounds__(1024) void k_sel(const int* __restrict__ rnd,
                                              float* __restrict__ mask_out) {
    extern __shared__ unsigned int dyn[];
    __shared__ int hist[256];
    __shared__ int sfxsum[257];
    __shared__ int warp_tot[32];
    __shared__ unsigned int s_prefix;
    __shared__ int s_need;

    int b = blockIdx.x;
    int tid = threadIdx.x;
    int lane = tid & 31, wrp = tid >> 5;

    for (int j = tid; j < NUM_OVER; j += 1024)
        dyn[j] = g_okey[b*NUM_OVER + j];
    if (tid == 0) { s_prefix = 0u; s_need = STEP1; }
    __syncthreads();

    for (int lvl = 0; lvl < 4; lvl++) {
        int shift = 24 - 8*lvl;
        unsigned int hi_mask = lvl ? (0xFFFFFFFFu << (shift + 8)) : 0u;
        unsigned int pref = s_prefix;
        int need = s_need;
        if (tid < 256) hist[tid] = 0;
        __syncthreads();
#pragma unroll
        for (int jj = 0; jj < CHUNK; jj++) {
            unsigned int ok = dyn[tid*CHUNK + jj];
            if ((ok & hi_mask) == pref) atomicAdd(&hist[(ok >> shift) & 255], 1);
        }
        __syncthreads();
        int x = (tid < 256) ? hist[255 - tid] : 0;
#pragma unroll
        for (int o = 1; o < 32; o <<= 1) {
            int y = __shfl_up_sync(0xFFFFFFFFu, x, o);
            if (lane >= o) x += y;
        }
        if (tid < 256 && lane == 31) warp_tot[wrp] = x;
        __syncthreads();
        if (tid < 256) {
            int basew = 0;
            for (int wq = 0; wq < wrp; wq++) basew += warp_tot[wq];
            sfxsum[255 - tid] = x + basew;
        }
        __syncthreads();
        if (tid < 256) {
            int S  = sfxsum[tid];
            int S1 = (tid == 255) ? 0 : sfxsum[tid + 1];
            if (S >= need && S1 < need) {
                s_prefix = pref | ((unsigned int)tid << shift);
                s_need = need - S1;
            }
        }
        __syncthreads();
    }
    unsigned int T = s_prefix;
    int need = s_need;

    unsigned int okv[CHUNK];
    int localeq = 0;
#pragma unroll
    for (int jj = 0; jj < CHUNK; jj++) {
        okv[jj] = dyn[tid*CHUNK + jj];
        localeq += (okv[jj] == T);
    }
    {
        int x = localeq;
#pragma unroll
        for (int o = 1; o < 32; o <<= 1) {
            int y = __shfl_up_sync(0xFFFFFFFFu, x, o);
            if (lane >= o) x += y;
        }
        if (lane == 31) warp_tot[wrp] = x;
        __syncthreads();
        int basew = 0;
        for (int wq = 0; wq < wrp; wq++) basew += warp_tot[wq];
        int rank = basew + x - localeq;
        unsigned int selmask = 0;
#pragma unroll
        for (int jj = 0; jj < CHUNK; jj++) {
            bool sel = okv[jj] > T;
            if (okv[jj] == T) { sel = (rank < need); rank++; }
            if (sel) selmask |= 1u << jj;
        }
        __syncthreads();
        for (int w = tid; w < NWORDS; w += 1024) dyn[w] = 0u;
        __syncthreads();
#pragma unroll
        for (int jj = 0; jj < CHUNK; jj++)
            if ((selmask >> jj) & 1u) {
                int lin = rnd[tid*CHUNK + jj];
                atomicOr(&dyn[lin >> 5], 1u << (lin & 31));
            }
    }
    for (int i = tid; i < STEP2; i += 1024) {
        int lin = rnd[HH*WW - STEP2 + i];
        atomicOr(&dyn[lin >> 5], 1u << (lin & 31));
    }
    __syncthreads();

    {
        int w0 = tid * 8;
        unsigned int words[8];
        int cnt = 0;
#pragma unroll
        for (int q = 0; q < 8; q++) { words[q] = dyn[w0 + q]; cnt += __popc(words[q]); }
        int incl = cnt;
#pragma unroll
        for (int o = 1; o < 32; o <<= 1) {
            int v = __shfl_up_sync(0xFFFFFFFFu, incl, o);
            if (lane >= o) incl += v;
        }
        if (lane == 31) warp_tot[wrp] = incl;
        __syncthreads();
        int basew = 0;
        for (int wq = 0; wq < wrp; wq++) basew += warp_tot[wq];
        int offset = basew + incl - cnt;
#pragma unroll
        for (int q = 0; q < 8; q++) {
            unsigned int m = words[q];
            int linbase = (w0 + q) * 32;
            while (m) {
                int bpos = __ffs(m) - 1; m &= m - 1;
                int lin = linbase + bpos;
                g_pts[b*NPTS + offset] = lin;
                mask_out[b*HH*WW + lin] = 1.0f;
                offset++;
            }
        }
    }
}

// =========================================================================
// k_sample (unchanged): one block per point, 256 threads = channels.
// =========================================================================
__global__ __launch_bounds__(256) void k_sample(const float* __restrict__ fine,
                                                const float* __restrict__ coarse) {
    int g = blockIdx.x;
    int b = g >> 11;
    int ch = threadIdx.x;
    int idx = g_pts[g];
    int h = idx >> 9, w = idx & 511;
    float yf = (float)h * 0.5f - 0.25f;
    float xf = (float)w * 0.5f - 0.25f;
    int y0 = (int)floorf(yf); float sfy = yf - (float)y0;
    int x0 = (int)floorf(xf); float sfx = xf - (float)x0;
    int sy0 = min(max(y0,   0), FHW-1), sy1 = min(max(y0+1, 0), FHW-1);
    int sx0 = min(max(x0,   0), FHW-1), sx1 = min(max(x0+1, 0), FHW-1);
    const float* pf = fine + ((size_t)b * CF + ch) * (FHW * FHW);
    float v00, v01, v10, v11;
    if ((sx1 == sx0 + 1) && ((sx0 & 1) == 0)) {
        float2 aa = *(const float2*)(pf + sy0*FHW + sx0);
        float2 dd = *(const float2*)(pf + sy1*FHW + sx0);
        v00 = aa.x; v01 = aa.y; v10 = dd.x; v11 = dd.y;
    } else {
        v00 = pf[sy0*FHW + sx0]; v01 = pf[sy0*FHW + sx1];
        v10 = pf[sy1*FHW + sx0]; v11 = pf[sy1*FHW + sx1];
    }
    float top = v00 * (1.f - sfx) + v01 * sfx;
    float bot = v10 * (1.f - sfx) + v11 * sfx;
    g_flat[(size_t)g * CF + ch] = top * (1.f - sfy) + bot * sfy;

    if (ch < NCc) {
        float yc = (float)h * 0.25f - 0.375f;
        float xc = (float)w * 0.25f - 0.375f;
        int cy = (int)floorf(yc); float cfy = yc - (float)cy;
        int cx = (int)floorf(xc); float cfx = xc - (float)cx;
        int cy0 = min(max(cy,   0), CHW-1), cy1 = min(max(cy+1, 0), CHW-1);
        int cx0 = min(max(cx,   0), CHW-1), cx1 = min(max(cx+1, 0), CHW-1);
        const float* pc = coarse + ((size_t)b * NCc + ch) * (CHW * CHW);
        float c00 = pc[cy0*CHW + cx0], c01 = pc[cy0*CHW + cx1];
        float c10 = pc[cy1*CHW + cx0], c11 = pc[cy1*CHW + cx1];
        float ctop = c00 * (1.f - cfx) + c01 * cfx;
        float cbot = c10 * (1.f - cfx) + c11 * cfx;
        g_cflat[g*NCc + ch] = ctop * (1.f - cfy) + cbot * cfy;
    }
}

// =========================================================================
// k_mlp: 512 threads, TWO independent 8-row groups per block (half=tid>>8).
// Same weight addresses in both halves (L1 reuse); cb processed in explicit
// 4-deep LDG batches to hide L2 latency. Per-row math bit-identical.
// =========================================================================
__global__ __launch_bounds__(512) void k_mlp(const float* __restrict__ w3,
                                             const float* __restrict__ pa,
                                             float* __restrict__ out) {
    extern __shared__ float sm[];
    float* xsp = sm;                         // 2 halves x 4 pairs x 260 x2
    float* l1p = xsp + 2*HTILE;              // same
    float* l2s = l1p + 2*HTILE;              // 16 x 128
    float* w3s = l2s + RPB*128;              // 396 (+4)

    int tid = threadIdx.x;
    int g0 = blockIdx.x * RPB;
    float a = *pa;
    int hf = tid >> 8;                       // 0/1: which 8-row group
    int t  = tid & 255;
    float* xh = xsp + hf*HTILE;
    float* lh = l1p + hf*HTILE;

    // ---- load rows (coalesced) into per-half pair tiles ----
    for (int q = tid; q < RPB*FEAT_PAD; q += 512) {
        int r = q / FEAT_PAD, c = q - r*FEAT_PAD;
        float v = 0.f;
        if (c < FEAT_DIM) {
            int f = (g0 + r) * FEAT_DIM + c;
            v = (f < FINE_FLAT) ? g_flat[f] : g_cflat[f - FINE_FLAT];
        }
        int hh = r >> 3, rl = r & 7;
        int pi = hh*HTILE + ((rl >> 1) * FEAT_PAD + c) * 2 + (rl & 1);
        xsp[pi] = v;
        if (c >= 256) l1p[pi] = v;
    }
    for (int q = tid; q < NCc*131; q += 512) w3s[q] = w3[q];
    __syncthreads();

    // ---- layer 1: 259 -> 256, prelu (4 pairs per thread, per half) ----
    {
        unsigned long long accp[HPAIR];
#pragma unroll
        for (int pr = 0; pr < HPAIR; pr++) accp[pr] = 0ull;
        const float4* w1p4 = (const float4*)g_w1p;

#define L1_CB(CB, WV) do {                                                   \
            unsigned long long wp0 = pk2((WV).x, (WV).x),                    \
                               wp1 = pk2((WV).y, (WV).y),                    \
                               wp2 = pk2((WV).z, (WV).z),                    \
                               wp3 = pk2((WV).w, (WV).w);                    \
            _Pragma("unroll")                                                \
            for (int pr = 0; pr < HPAIR; pr++) {                             \
                const ulonglong2* xp =                                       \
                    (const ulonglong2*)&xh[(pr*FEAT_PAD + (CB)*4) * 2];      \
                ulonglong2 u0 = xp[0], u1 = xp[1];                           \
                fma2(accp[pr], wp0, u0.x);                                   \
                fma2(accp[pr], wp1, u0.y);                                   \
                fma2(accp[pr], wp2, u1.x);                                   \
                fma2(accp[pr], wp3, u1.y);                                   \
            }                                                                \
        } while (0)

        for (int cb0 = 0; cb0 < 64; cb0 += 4) {
            float4 a0 = w1p4[(cb0+0)*256 + t];
            float4 a1 = w1p4[(cb0+1)*256 + t];
            float4 a2 = w1p4[(cb0+2)*256 + t];
            float4 a3 = w1p4[(cb0+3)*256 + t];
            L1_CB(cb0+0, a0); L1_CB(cb0+1, a1);
            L1_CB(cb0+2, a2); L1_CB(cb0+3, a3);
        }
        { float4 a4 = w1p4[64*256 + t]; L1_CB(64, a4); }
#undef L1_CB

#pragma unroll
        for (int pr = 0; pr < HPAIR; pr++) {
            float lo, hi; upk2(accp[pr], lo, hi);
            lo = lo >= 0.f ? lo : a * lo;
            hi = hi >= 0.f ? hi : a * hi;
            ((float2*)lh)[pr*FEAT_PAD + t] = make_float2(lo, hi);
        }
    }
    __syncthreads();

    // ---- layer 2: 259 -> 128, prelu (2 pairs per thread, per half) ----
    {
        int o2 = t & 127;
        int rh = t >> 7;                     // 0/1 within half
        unsigned long long acc2[2];
        acc2[0] = 0ull; acc2[1] = 0ull;
        const float4* w2p4 = (const float4*)g_w2p;

#define L2_CB(CB, WV) do {                                                   \
            unsigned long long wp0 = pk2((WV).x, (WV).x),                    \
                               wp1 = pk2((WV).y, (WV).y),                    \
                               wp2 = pk2((WV).z, (WV).z),                    \
                               wp3 = pk2((WV).w, (WV).w);                    \
            _Pragma("unroll")                                                \
            for (int pp = 0; pp < 2; pp++) {                                 \
                int pr = rh*2 + pp;                                          \
                const ulonglong2* xp =                                       \
                    (const ulonglong2*)&lh[(pr*FEAT_PAD + (CB)*4) * 2];      \
                ulonglong2 u0 = xp[0], u1 = xp[1];                           \
                fma2(acc2[pp], wp0, u0.x);                                   \
                fma2(acc2[pp], wp1, u0.y);                                   \
                fma2(acc2[pp], wp2, u1.x);                                   \
                fma2(acc2[pp], wp3, u1.y);                                   \
            }                                                                \
        } while (0)

        for (int cb0 = 0; cb0 < 64; cb0 += 4) {
            float4 a0 = w2p4[(cb0+0)*128 + o2];
            float4 a1 = w2p4[(cb0+1)*128 + o2];
            float4 a2 = w2p4[(cb0+2)*128 + o2];
            float4 a3 = w2p4[(cb0+3)*128 + o2];
            L2_CB(cb0+0, a0); L2_CB(cb0+1, a1);
            L2_CB(cb0+2, a2); L2_CB(cb0+3, a3);
        }
        { float4 a4 = w2p4[64*128 + o2]; L2_CB(64, a4); }
#undef L2_CB

#pragma unroll
        for (int pp = 0; pp < 2; pp++) {
            int pr = rh*2 + pp;
            float lo, hi; upk2(acc2[pp], lo, hi);
            lo = lo >= 0.f ? lo : a * lo;
            hi = hi >= 0.f ? hi : a * hi;
            l2s[hf*1024 + (2*pr  )*128 + o2] = lo;
            l2s[hf*1024 + (2*pr+1)*128 + o2] = hi;
        }
    }
    __syncthreads();

    // ---- layer 3: 131 -> 3 (per half: 8 rows x 3 outputs) ----
    if (t < 8*NCc) {
        int r = t / 3, oo = t % 3;
        float s = 0.f;
        for (int c = 0; c < 128; c++)
            s = fmaf(w3s[oo*131 + c], l2s[hf*1024 + r*128 + c], s);
#pragma unroll
        for (int q = 0; q < 3; q++) {
            float xt = xh[((r >> 1)*FEAT_PAD + 256 + q)*2 + (r & 1)];
            s = fmaf(w3s[oo*131 + 128 + q], xt, s);
        }
        int g = g0 + hf*8 + r;
        int b = g >> 11, n = g & 2047;
        out[(b*NCc + oo)*NPTS + n] = s;
    }
}

// ---------------- launch ----------------
extern "C" void kernel_launch(void* const* d_in, const int* in_sizes, int n_in,
                              void* d_out, int out_size) {
    const float* fine   = (const float*)d_in[0];
    const float* coarse = (const float*)d_in[1];
    const float* w1     = (const float*)d_in[2];
    const float* w2     = (const float*)d_in[3];
    const float* w3     = (const float*)d_in[4];
    const float* pa     = (const float*)d_in[5];
    const int*   rnd    = (const int*)d_in[6];
    float* out = (float*)d_out;

    static int configured = 0;
    int mlp_smem = (2*HTILE*2 + RPB*128 + 400) * (int)sizeof(float);
    if (!configured) {
        cudaFuncSetAttribute(k_sel, cudaFuncAttributeMaxDynamicSharedMemorySize,
                             NWORDS * (int)sizeof(unsigned int));
        cudaFuncSetAttribute(k_mlp, cudaFuncAttributeMaxDynamicSharedMemorySize,
                             mlp_smem);
        configured = 1;
    }

    cudaMemsetAsync(out + OUT_OFF, 0, (size_t)MASK_SIZE * sizeof(float), 0);
    k_unc<<<UNC_BLOCKS + REPACK_BLOCKS, 1024>>>(coarse, rnd, w1, w2);
    k_sel<<<BB, 1024, NWORDS * sizeof(unsigned int)>>>(rnd, out + OUT_OFF);
    k_sample<<<NROWS, 256>>>(fine, coarse);
    k_mlp<<<NROWS/RPB, 512, mlp_smem>>>(w3, pa, out);
    (void)in_sizes; (void)n_in; (void)out_size;
}